// round 10
// baseline (speedup 1.0000x reference)
#include <cuda_runtime.h>
#include <cuda_fp16.h>
#include <math.h>

#define NN 30000
#define EE 480000
#define CSRN (EE + NN)      // csr with self loops appended per row
#define FIN 128
#define DD 32
#define HH 4
#define HD 128
#define GG 128
#define TT 10
#define NGB 470             // gemm blocks: 2 * ceil(NN/128)

// ---------------- scratch (device globals; no allocation allowed) ----------------
__device__ __half g_xlh[NN*HD];    // xl in fp16 (conv gather operand)
__device__ float  g_xr[NN*HD];     // xr in fp32
__device__ float  g_hfeat[NN*DD];
__device__ int2   g_sd[EE];        // packed (src,dst)
__device__ int    g_csr_src[CSRN];
__device__ int    g_deg[NN];       // zero at load; re-zeroed by k_scan each run
__device__ int    g_fill[NN];
__device__ int    g_rowptr[NN+1];  // self-loop-inclusive (shifted by +idx)
__device__ int    g_batch[NN];
__device__ float  g_pool[GG*DD];

// float atomic max via sign-split (correct incl. -0.0; init = -inf)
__device__ __forceinline__ void atomicMaxF(float* addr, float v) {
  unsigned u = __float_as_uint(v);
  if (u >> 31) atomicMin((unsigned*)addr, u);
  else         atomicMax((int*)addr, (int)u);
}

// ---------------- fused: dual SGEMM (blocks < NGB) + edge prep (blocks >= NGB) ----------------
__global__ __launch_bounds__(256) void k_gemm_prep(
    const float* __restrict__ A,
    const float* __restrict__ Wl, const float* __restrict__ bl,
    const float* __restrict__ Wr, const float* __restrict__ br,
    int M, int K,
    const void* __restrict__ ei, const void* __restrict__ bt) {
  if (blockIdx.x >= NGB) {                 // ---- prep branch ----
    __shared__ int s64;
    if (threadIdx.x == 0) {
      const long long* p = (const long long*)ei;
      int ok = 1;
      #pragma unroll
      for (int q = 0; q < 16; q++) { long long v = p[q]; if (v < 0 || v >= NN) ok = 0; }
      s64 = ok;
    }
    __syncthreads();
    int is64 = s64;
    int i = (blockIdx.x - NGB)*256 + threadIdx.x;
    if (i < EE) {
      int s, d;
      if (is64) {
        const long long* p = (const long long*)ei;
        s = (int)p[i]; d = (int)p[EE + i];
      } else {
        const int* p = (const int*)ei;
        s = p[i]; d = p[EE + i];
      }
      g_sd[i] = make_int2(s, d);
      atomicAdd(&g_deg[d], 1);
    }
    if (i < NN)
      g_batch[i] = is64 ? (int)((const long long*)bt)[i] : ((const int*)bt)[i];
    if (i < GG*DD) g_pool[i] = -INFINITY;
    return;
  }
  // ---- GEMM branch ----
  __shared__ float As[16][132];
  __shared__ float Bs[16][132];
  const int bm = (blockIdx.x >> 1) * 128;
  const int half_out = (blockIdx.x & 1) == 0;   // 0 -> xl(half), 1 -> xr(float)
  const int tid = threadIdx.x;
  const int tr = tid >> 4;
  const int tc = tid & 15;
  const float* W = half_out ? Wl : Wr;
  const float* bias = half_out ? bl : br;
  float acc[8][8] = {};
  for (int k0 = 0; k0 < K; k0 += 16) {
    #pragma unroll
    for (int i = 0; i < 2; i++) {
      int li = tid + i*256;
      int r = li >> 2;
      int kk = (li & 3) * 4;
      int m = bm + r;
      float4 v = make_float4(0.f,0.f,0.f,0.f);
      if (m < M) v = *(const float4*)&A[(size_t)m*K + k0 + kk];
      As[kk+0][r] = v.x; As[kk+1][r] = v.y; As[kk+2][r] = v.z; As[kk+3][r] = v.w;
    }
    #pragma unroll
    for (int i = 0; i < 2; i++) {
      int li = tid + i*256;
      int r = li >> 2;
      int kk = (li & 3) * 4;
      float4 v = *(const float4*)&W[(size_t)r*K + k0 + kk];
      Bs[kk+0][r] = v.x; Bs[kk+1][r] = v.y; Bs[kk+2][r] = v.z; Bs[kk+3][r] = v.w;
    }
    __syncthreads();
    #pragma unroll
    for (int k = 0; k < 16; k++) {
      float4 a0 = *(const float4*)&As[k][tr*8];
      float4 a1 = *(const float4*)&As[k][tr*8 + 4];
      float4 b0 = *(const float4*)&Bs[k][tc*8];
      float4 b1 = *(const float4*)&Bs[k][tc*8 + 4];
      float a[8] = {a0.x,a0.y,a0.z,a0.w,a1.x,a1.y,a1.z,a1.w};
      float b[8] = {b0.x,b0.y,b0.z,b0.w,b1.x,b1.y,b1.z,b1.w};
      #pragma unroll
      for (int i = 0; i < 8; i++)
        #pragma unroll
        for (int j = 0; j < 8; j++) acc[i][j] += a[i]*b[j];
    }
    __syncthreads();
  }
  float bia[8];
  #pragma unroll
  for (int j = 0; j < 8; j++) bia[j] = bias[tc*8 + j];
  #pragma unroll
  for (int i = 0; i < 8; i++) {
    int m = bm + tr*8 + i;
    if (m >= M) continue;
    if (half_out) {
      __half2 h[4];
      #pragma unroll
      for (int j = 0; j < 4; j++)
        h[j] = __floats2half2_rn(acc[i][2*j]+bia[2*j], acc[i][2*j+1]+bia[2*j+1]);
      *(uint4*)&g_xlh[(size_t)m*HD + tc*8] = *(uint4*)h;
    } else {
      float4 o0 = make_float4(acc[i][0]+bia[0], acc[i][1]+bia[1], acc[i][2]+bia[2], acc[i][3]+bia[3]);
      float4 o1 = make_float4(acc[i][4]+bia[4], acc[i][5]+bia[5], acc[i][6]+bia[6], acc[i][7]+bia[7]);
      *(float4*)&g_xr[(size_t)m*HD + tc*8]     = o0;
      *(float4*)&g_xr[(size_t)m*HD + tc*8 + 4] = o1;
    }
  }
}

// single-block exclusive scan over g_deg -> self-loop-inclusive g_rowptr; seeds g_fill; re-zeroes g_deg
__global__ __launch_bounds__(1024) void k_scan() {
  __shared__ int ssum[1024];
  const int per = (NN + 1023)/1024;  // 30
  int t = threadIdx.x;
  int base = t*per;
  int vals[32];
  int local = 0;
  for (int i = 0; i < per; i++) {
    int idx = base + i;
    int v = 0;
    if (idx < NN) { v = g_deg[idx]; g_deg[idx] = 0; }   // zero for next replay
    vals[i] = local; local += v;
  }
  ssum[t] = local;
  __syncthreads();
  for (int off = 1; off < 1024; off <<= 1) {
    int v = (t >= off) ? ssum[t-off] : 0;
    __syncthreads();
    ssum[t] += v;
    __syncthreads();
  }
  int prev = (t == 0) ? 0 : ssum[t-1];
  for (int i = 0; i < per; i++) {
    int idx = base + i;
    if (idx < NN) {
      int rp = prev + vals[i] + idx;     // +idx: one self-loop slot per preceding row
      g_rowptr[idx] = rp;
      g_fill[idx]   = rp;                // edges fill from row start
    }
  }
  if (t == 1023) g_rowptr[NN] = ssum[1023] + NN;
}

// fill CSR edges (atomic position) + write self-loop at end of each row
__global__ void k_fill() {
  int i = blockIdx.x*blockDim.x + threadIdx.x;
  if (i < EE) {
    int2 sd = g_sd[i];
    int pos = atomicAdd(&g_fill[sd.y], 1);
    g_csr_src[pos] = sd.x;
  }
  if (i < NN)
    g_csr_src[g_rowptr[i+1] - 1] = i;    // self loop (slot rowptr[i]+deg, no conflict)
}

// ---------------- fused GATv2: 2 nodes per warp, 16 lanes per node ----------------
// 256 thr = 8 warps = 16 nodes/block. Lane sl (0..15 within half-warp) holds features
// sl*8..sl*8+7 (uint4 fp16 gather) — all in head sl>>2, so the alpha reduction is a
// 2-shuffle 4-lane reduce. One LDG.128 serves 2 edges (one per half-warp).
// Double-buffered prefetch. exp without max-subtraction (softmax shift-invariant).
__global__ __launch_bounds__(256) void k_conv_fused(
    const float* __restrict__ att, const float* __restrict__ cb,
    const float* __restrict__ lw, const float* __restrict__ lb,
    float* __restrict__ outp, int do_pool) {
  __shared__ float stmp[16][132];
  int t = threadIdx.x;
  int w = t >> 5, lane = t & 31;
  int half = lane >> 4, sl = lane & 15;
  int node = w*2 + half;                  // 0..15 within block
  int d = blockIdx.x*16 + node;           // grid = NN/16 = 1875 exactly

  float xr[8], at[8];
  {
    float4 a0 = *(const float4*)&g_xr[(size_t)d*HD + sl*8];
    float4 a1 = *(const float4*)&g_xr[(size_t)d*HD + sl*8 + 4];
    xr[0]=a0.x; xr[1]=a0.y; xr[2]=a0.z; xr[3]=a0.w;
    xr[4]=a1.x; xr[5]=a1.y; xr[6]=a1.z; xr[7]=a1.w;
    float4 b0 = *(const float4*)&att[sl*8];
    float4 b1 = *(const float4*)&att[sl*8 + 4];
    at[0]=b0.x; at[1]=b0.y; at[2]=b0.z; at[3]=b0.w;
    at[4]=b1.x; at[5]=b1.y; at[6]=b1.z; at[7]=b1.w;
  }
  float acc[8] = {0.f,0.f,0.f,0.f,0.f,0.f,0.f,0.f};
  float den = 0.f;
  int rs = __ldg(&g_rowptr[d]), re = __ldg(&g_rowptr[d+1]);
  int iters = re - rs;                    // >= 1 (self loop)
  int maxit = max(iters, __shfl_xor_sync(0xffffffffu, iters, 16));

  int s0 = __ldg(&g_csr_src[rs]);
  uint4 hc = *(const uint4*)&g_xlh[(size_t)s0*HD + sl*8];
  for (int i = 0; i < maxit; i++) {
    int nxt = (i + 1 < iters) ? rs + i + 1 : re - 1;
    int sn = __ldg(&g_csr_src[nxt]);
    uint4 hn = *(const uint4*)&g_xlh[(size_t)sn*HD + sl*8];   // prefetch next

    float f[8];
    float2 c0 = __half22float2(*(const __half2*)&hc.x);
    float2 c1 = __half22float2(*(const __half2*)&hc.y);
    float2 c2 = __half22float2(*(const __half2*)&hc.z);
    float2 c3 = __half22float2(*(const __half2*)&hc.w);
    f[0]=c0.x; f[1]=c0.y; f[2]=c1.x; f[3]=c1.y;
    f[4]=c2.x; f[5]=c2.y; f[6]=c3.x; f[7]=c3.y;

    float sum = 0.f;
    #pragma unroll
    for (int k = 0; k < 8; k++) {
      float v = f[k] + xr[k];
      v = fmaxf(v, 0.2f*v);               // leaky_relu(0.2)
      sum += v * at[k];
    }
    sum += __shfl_xor_sync(0xffffffffu, sum, 1);
    sum += __shfl_xor_sync(0xffffffffu, sum, 2);  // head alpha in each 4-lane group
    float ex = (i < iters) ? __expf(sum) : 0.f;
    den += ex;
    #pragma unroll
    for (int k = 0; k < 8; k++) acc[k] += ex * f[k];
    hc = hn;
  }

  float inv = 1.0f / (den * (float)iters);        // mean over deg+1 (self incl.)
  {
    float4 cb0 = *(const float4*)&cb[sl*8];
    float4 cb1 = *(const float4*)&cb[sl*8 + 4];
    float4 o0 = make_float4(acc[0]*inv + cb0.x, acc[1]*inv + cb0.y,
                            acc[2]*inv + cb0.z, acc[3]*inv + cb0.w);
    float4 o1 = make_float4(acc[4]*inv + cb1.x, acc[5]*inv + cb1.y,
                            acc[6]*inv + cb1.z, acc[7]*inv + cb1.w);
    *(float4*)&stmp[node][sl*8]     = o0;
    *(float4*)&stmp[node][sl*8 + 4] = o1;
  }
  __syncwarp();

  // Linear HD->DD: full warp per node (2 nodes sequentially); lane -> output feature lane
  const float* lwr = &lw[(size_t)lane*HD];
  #pragma unroll
  for (int nd = 0; nd < 2; nd++) {
    int nodeb = w*2 + nd;
    int db = blockIdx.x*16 + nodeb;
    float o = lb[lane];
    #pragma unroll
    for (int k = 0; k < HD; k += 4) {
      float4 wv = *(const float4*)&lwr[k];
      o += stmp[nodeb][k+0]*wv.x + stmp[nodeb][k+1]*wv.y
         + stmp[nodeb][k+2]*wv.z + stmp[nodeb][k+3]*wv.w;
    }
    if (do_pool) atomicMaxF(&g_pool[g_batch[db]*DD + lane], o);
    else         outp[(size_t)db*DD + lane] = o;
  }
}

// ---------------- head MLP ----------------
__global__ void k_final(const float* __restrict__ fc1W, const float* __restrict__ fc1b,
                        const float* __restrict__ fc2W, const float* __restrict__ fc2b,
                        float* __restrict__ out) {
  int g = threadIdx.x;
  if (g >= GG) return;
  float y[DD];
  #pragma unroll
  for (int j = 0; j < DD; j++) {
    float acc = fc1b[j];
    #pragma unroll
    for (int k = 0; k < DD; k++) acc += g_pool[g*DD + k] * fc1W[j*DD + k];
    y[j] = fmaxf(acc, 0.f);
  }
  #pragma unroll
  for (int i = 0; i < TT; i++) {
    float acc = fc2b[i];
    #pragma unroll
    for (int j = 0; j < DD; j++) acc += y[j] * fc2W[i*DD + j];
    out[g*TT + i] = acc;
  }
}

// ---------------- driver ----------------
extern "C" void kernel_launch(void* const* d_in, const int* in_sizes, int n_in,
                              void* d_out, int out_size) {
  const float* x   = (const float*)d_in[0];
  const void*  ei  = d_in[1];
  const void*  bt  = d_in[2];
  const float* Wl0 = (const float*)d_in[3];  const float* bl0 = (const float*)d_in[4];
  const float* Wr0 = (const float*)d_in[5];  const float* br0 = (const float*)d_in[6];
  const float* at0 = (const float*)d_in[7];  const float* cb0 = (const float*)d_in[8];
  const float* lw0 = (const float*)d_in[9];  const float* lb0 = (const float*)d_in[10];
  const float* Wl1 = (const float*)d_in[11]; const float* bl1 = (const float*)d_in[12];
  const float* Wr1 = (const float*)d_in[13]; const float* br1 = (const float*)d_in[14];
  const float* at1 = (const float*)d_in[15]; const float* cb1 = (const float*)d_in[16];
  const float* lw1 = (const float*)d_in[17]; const float* lb1 = (const float*)d_in[18];
  const float* f1W = (const float*)d_in[19]; const float* f1b = (const float*)d_in[20];
  const float* f2W = (const float*)d_in[21]; const float* f2b = (const float*)d_in[22];
  float* out = (float*)d_out;

  float* hf;
  cudaGetSymbolAddress((void**)&hf, g_hfeat);

  const int prep_blocks = (EE + 255)/256;           // 1875

  // idx 0: gemm0 + prep fused (independent work, overlapped)
  k_gemm_prep<<<NGB + prep_blocks, 256>>>(x, Wl0, bl0, Wr0, br0, NN, FIN, ei, bt);
  k_scan<<<1, 1024>>>();                            // idx 1
  k_fill<<<prep_blocks, 256>>>();                   // idx 2
  k_conv_fused<<<NN/16, 256>>>(at0, cb0, lw0, lb0, hf, 0);   // idx 3 -> profiled
  k_gemm_prep<<<NGB, 256>>>(hf, Wl1, bl1, Wr1, br1, NN, DD, ei, bt);  // idx 4
  k_conv_fused<<<NN/16, 256>>>(at1, cb1, lw1, lb1, nullptr, 1);       // idx 5
  k_final<<<1, 128>>>(f1W, f1b, f2W, f2b, out);     // idx 6
}

// round 11
// speedup vs baseline: 1.7228x; 1.7228x over previous
#include <cuda_runtime.h>
#include <cuda_fp16.h>
#include <math.h>

#define NN 30000
#define EE 480000
#define CSRN (EE + NN)      // csr with self loops appended per row
#define FIN 128
#define DD 32
#define HH 4
#define HD 128
#define GG 128
#define TT 10
#define NGB 470             // gemm blocks: 2 * ceil(NN/128)

// ---------------- scratch (device globals; no allocation allowed) ----------------
__device__ __half g_xlh[NN*HD];    // xl in fp16 (conv gather operand)
__device__ float  g_xr[NN*HD];     // xr in fp32
__device__ float  g_tmp[NN*HD];    // conv output before the HD->DD linear
__device__ float  g_hfeat[NN*DD];
__device__ int2   g_sd[EE];        // packed (src,dst)
__device__ int    g_csr_src[CSRN];
__device__ int    g_deg[NN];       // zero at load; re-zeroed by k_scan each run
__device__ int    g_fill[NN];
__device__ int    g_rowptr[NN+1];  // self-loop-inclusive (shifted by +idx)
__device__ int    g_batch[NN];
__device__ float  g_pool[GG*DD];

// float atomic max via sign-split (correct incl. -0.0; init = -inf)
__device__ __forceinline__ void atomicMaxF(float* addr, float v) {
  unsigned u = __float_as_uint(v);
  if (u >> 31) atomicMin((unsigned*)addr, u);
  else         atomicMax((int*)addr, (int)u);
}

// ---------------- fused: dual SGEMM (blocks < NGB) + edge prep (blocks >= NGB) ----------------
__global__ __launch_bounds__(256) void k_gemm_prep(
    const float* __restrict__ A,
    const float* __restrict__ Wl, const float* __restrict__ bl,
    const float* __restrict__ Wr, const float* __restrict__ br,
    int M, int K,
    const void* __restrict__ ei, const void* __restrict__ bt) {
  if (blockIdx.x >= NGB) {                 // ---- prep branch ----
    __shared__ int s64;
    if (threadIdx.x == 0) {
      const long long* p = (const long long*)ei;
      int ok = 1;
      #pragma unroll
      for (int q = 0; q < 16; q++) { long long v = p[q]; if (v < 0 || v >= NN) ok = 0; }
      s64 = ok;
    }
    __syncthreads();
    int is64 = s64;
    int i = (blockIdx.x - NGB)*256 + threadIdx.x;
    if (i < EE) {
      int s, d;
      if (is64) {
        const long long* p = (const long long*)ei;
        s = (int)p[i]; d = (int)p[EE + i];
      } else {
        const int* p = (const int*)ei;
        s = p[i]; d = p[EE + i];
      }
      g_sd[i] = make_int2(s, d);
      atomicAdd(&g_deg[d], 1);
    }
    if (i < NN)
      g_batch[i] = is64 ? (int)((const long long*)bt)[i] : ((const int*)bt)[i];
    if (i < GG*DD) g_pool[i] = -INFINITY;
    return;
  }
  // ---- GEMM branch ----
  __shared__ float As[16][132];
  __shared__ float Bs[16][132];
  const int bm = (blockIdx.x >> 1) * 128;
  const int half_out = (blockIdx.x & 1) == 0;   // 0 -> xl(half), 1 -> xr(float)
  const int tid = threadIdx.x;
  const int tr = tid >> 4;
  const int tc = tid & 15;
  const float* W = half_out ? Wl : Wr;
  const float* bias = half_out ? bl : br;
  float acc[8][8] = {};
  for (int k0 = 0; k0 < K; k0 += 16) {
    #pragma unroll
    for (int i = 0; i < 2; i++) {
      int li = tid + i*256;
      int r = li >> 2;
      int kk = (li & 3) * 4;
      int m = bm + r;
      float4 v = make_float4(0.f,0.f,0.f,0.f);
      if (m < M) v = *(const float4*)&A[(size_t)m*K + k0 + kk];
      As[kk+0][r] = v.x; As[kk+1][r] = v.y; As[kk+2][r] = v.z; As[kk+3][r] = v.w;
    }
    #pragma unroll
    for (int i = 0; i < 2; i++) {
      int li = tid + i*256;
      int r = li >> 2;
      int kk = (li & 3) * 4;
      float4 v = *(const float4*)&W[(size_t)r*K + k0 + kk];
      Bs[kk+0][r] = v.x; Bs[kk+1][r] = v.y; Bs[kk+2][r] = v.z; Bs[kk+3][r] = v.w;
    }
    __syncthreads();
    #pragma unroll
    for (int k = 0; k < 16; k++) {
      float4 a0 = *(const float4*)&As[k][tr*8];
      float4 a1 = *(const float4*)&As[k][tr*8 + 4];
      float4 b0 = *(const float4*)&Bs[k][tc*8];
      float4 b1 = *(const float4*)&Bs[k][tc*8 + 4];
      float a[8] = {a0.x,a0.y,a0.z,a0.w,a1.x,a1.y,a1.z,a1.w};
      float b[8] = {b0.x,b0.y,b0.z,b0.w,b1.x,b1.y,b1.z,b1.w};
      #pragma unroll
      for (int i = 0; i < 8; i++)
        #pragma unroll
        for (int j = 0; j < 8; j++) acc[i][j] += a[i]*b[j];
    }
    __syncthreads();
  }
  float bia[8];
  #pragma unroll
  for (int j = 0; j < 8; j++) bia[j] = bias[tc*8 + j];
  #pragma unroll
  for (int i = 0; i < 8; i++) {
    int m = bm + tr*8 + i;
    if (m >= M) continue;
    if (half_out) {
      __half2 h[4];
      #pragma unroll
      for (int j = 0; j < 4; j++)
        h[j] = __floats2half2_rn(acc[i][2*j]+bia[2*j], acc[i][2*j+1]+bia[2*j+1]);
      *(uint4*)&g_xlh[(size_t)m*HD + tc*8] = *(uint4*)h;
    } else {
      float4 o0 = make_float4(acc[i][0]+bia[0], acc[i][1]+bia[1], acc[i][2]+bia[2], acc[i][3]+bia[3]);
      float4 o1 = make_float4(acc[i][4]+bia[4], acc[i][5]+bia[5], acc[i][6]+bia[6], acc[i][7]+bia[7]);
      *(float4*)&g_xr[(size_t)m*HD + tc*8]     = o0;
      *(float4*)&g_xr[(size_t)m*HD + tc*8 + 4] = o1;
    }
  }
}

// single-block exclusive scan over g_deg -> self-loop-inclusive g_rowptr; seeds g_fill; re-zeroes g_deg
__global__ __launch_bounds__(1024) void k_scan() {
  __shared__ int ssum[1024];
  const int per = (NN + 1023)/1024;  // 30
  int t = threadIdx.x;
  int base = t*per;
  int vals[32];
  int local = 0;
  for (int i = 0; i < per; i++) {
    int idx = base + i;
    int v = 0;
    if (idx < NN) { v = g_deg[idx]; g_deg[idx] = 0; }   // zero for next replay
    vals[i] = local; local += v;
  }
  ssum[t] = local;
  __syncthreads();
  for (int off = 1; off < 1024; off <<= 1) {
    int v = (t >= off) ? ssum[t-off] : 0;
    __syncthreads();
    ssum[t] += v;
    __syncthreads();
  }
  int prev = (t == 0) ? 0 : ssum[t-1];
  for (int i = 0; i < per; i++) {
    int idx = base + i;
    if (idx < NN) {
      int rp = prev + vals[i] + idx;     // +idx: one self-loop slot per preceding row
      g_rowptr[idx] = rp;
      g_fill[idx]   = rp;                // edges fill from row start
    }
  }
  if (t == 1023) g_rowptr[NN] = ssum[1023] + NN;
}

// fill CSR edges (atomic position) + write self-loop at end of each row
__global__ void k_fill() {
  int i = blockIdx.x*blockDim.x + threadIdx.x;
  if (i < EE) {
    int2 sd = g_sd[i];
    int pos = atomicAdd(&g_fill[sd.y], 1);
    g_csr_src[pos] = sd.x;
  }
  if (i < NN)
    g_csr_src[g_rowptr[i+1] - 1] = i;    // self loop (slot rowptr[i]+deg, no conflict)
}

// ---------------- lean GATv2 conv: 2 nodes/warp, 16 lanes/node, NO epilogue linear ----------------
// Lane sl (0..15) holds features sl*8..+7 (uint4 fp16 gather; head = sl>>2, 4-lane reduce).
// Writes tmp[d][:] = mean-softmax aggregate + cb. exp without max-subtraction.
__global__ __launch_bounds__(256) void k_conv(
    const float* __restrict__ att, const float* __restrict__ cb) {
  int t = threadIdx.x;
  int w = t >> 5, lane = t & 31;
  int half = lane >> 4, sl = lane & 15;
  int node = w*2 + half;
  int d = blockIdx.x*16 + node;           // grid = NN/16 = 1875 exactly

  float xr[8], at[8];
  {
    float4 a0 = *(const float4*)&g_xr[(size_t)d*HD + sl*8];
    float4 a1 = *(const float4*)&g_xr[(size_t)d*HD + sl*8 + 4];
    xr[0]=a0.x; xr[1]=a0.y; xr[2]=a0.z; xr[3]=a0.w;
    xr[4]=a1.x; xr[5]=a1.y; xr[6]=a1.z; xr[7]=a1.w;
    float4 b0 = *(const float4*)&att[sl*8];
    float4 b1 = *(const float4*)&att[sl*8 + 4];
    at[0]=b0.x; at[1]=b0.y; at[2]=b0.z; at[3]=b0.w;
    at[4]=b1.x; at[5]=b1.y; at[6]=b1.z; at[7]=b1.w;
  }
  float acc[8] = {0.f,0.f,0.f,0.f,0.f,0.f,0.f,0.f};
  float den = 0.f;
  int rs = __ldg(&g_rowptr[d]), re = __ldg(&g_rowptr[d+1]);
  int iters = re - rs;                    // >= 1 (self loop)
  int maxit = max(iters, __shfl_xor_sync(0xffffffffu, iters, 16));

  int s0 = __ldg(&g_csr_src[rs]);
  uint4 hc = *(const uint4*)&g_xlh[(size_t)s0*HD + sl*8];
  for (int i = 0; i < maxit; i++) {
    int nxt = (i + 1 < iters) ? rs + i + 1 : re - 1;
    int sn = __ldg(&g_csr_src[nxt]);
    uint4 hn = *(const uint4*)&g_xlh[(size_t)sn*HD + sl*8];   // prefetch next

    float f[8];
    float2 c0 = __half22float2(*(const __half2*)&hc.x);
    float2 c1 = __half22float2(*(const __half2*)&hc.y);
    float2 c2 = __half22float2(*(const __half2*)&hc.z);
    float2 c3 = __half22float2(*(const __half2*)&hc.w);
    f[0]=c0.x; f[1]=c0.y; f[2]=c1.x; f[3]=c1.y;
    f[4]=c2.x; f[5]=c2.y; f[6]=c3.x; f[7]=c3.y;

    float sum = 0.f;
    #pragma unroll
    for (int k = 0; k < 8; k++) {
      float v = f[k] + xr[k];
      v = fmaxf(v, 0.2f*v);               // leaky_relu(0.2)
      sum += v * at[k];
    }
    sum += __shfl_xor_sync(0xffffffffu, sum, 1);
    sum += __shfl_xor_sync(0xffffffffu, sum, 2);  // head alpha in each 4-lane group
    float ex = (i < iters) ? __expf(sum) : 0.f;
    den += ex;
    #pragma unroll
    for (int k = 0; k < 8; k++) acc[k] += ex * f[k];
    hc = hn;
  }

  float inv = 1.0f / (den * (float)iters);        // mean over deg+1 (self incl.)
  float4 cb0 = *(const float4*)&cb[sl*8];
  float4 cb1 = *(const float4*)&cb[sl*8 + 4];
  float4 o0 = make_float4(acc[0]*inv + cb0.x, acc[1]*inv + cb0.y,
                          acc[2]*inv + cb0.z, acc[3]*inv + cb0.w);
  float4 o1 = make_float4(acc[4]*inv + cb1.x, acc[5]*inv + cb1.y,
                          acc[6]*inv + cb1.z, acc[7]*inv + cb1.w);
  *(float4*)&g_tmp[(size_t)d*HD + sl*8]     = o0;
  *(float4*)&g_tmp[(size_t)d*HD + sl*8 + 4] = o1;
}

// ---------------- HD->DD linear as tiled GEMM: C = tmp @ lw^T + lb ----------------
// BM=128, N=32, BK=16, 256 threads, 8x2 microtile. lw read once per block via smem.
// do_pool: atomicMax into g_pool instead of storing hfeat.
__global__ __launch_bounds__(256) void k_lin(
    const float* __restrict__ lw, const float* __restrict__ lb,
    float* __restrict__ Cout, int do_pool) {
  __shared__ float As[16][132];
  __shared__ float Bs[16][36];
  const int bm = blockIdx.x * 128;
  const int tid = threadIdx.x;
  const int tr = tid >> 4;      // 0..15 -> 8 rows each
  const int tc = tid & 15;      // 0..15 -> 2 cols each
  float acc[8][2] = {};
  for (int k0 = 0; k0 < HD; k0 += 16) {
    #pragma unroll
    for (int i = 0; i < 2; i++) {
      int li = tid + i*256;
      int r = li >> 2;
      int kk = (li & 3) * 4;
      int m = bm + r;
      float4 v = make_float4(0.f,0.f,0.f,0.f);
      if (m < NN) v = *(const float4*)&g_tmp[(size_t)m*HD + k0 + kk];
      As[kk+0][r] = v.x; As[kk+1][r] = v.y; As[kk+2][r] = v.z; As[kk+3][r] = v.w;
    }
    if (tid < 128) {
      int r = tid >> 2;         // 0..31
      int kk = (tid & 3) * 4;
      float4 v = *(const float4*)&lw[(size_t)r*HD + k0 + kk];
      Bs[kk+0][r] = v.x; Bs[kk+1][r] = v.y; Bs[kk+2][r] = v.z; Bs[kk+3][r] = v.w;
    }
    __syncthreads();
    #pragma unroll
    for (int k = 0; k < 16; k++) {
      float4 a0 = *(const float4*)&As[k][tr*8];
      float4 a1 = *(const float4*)&As[k][tr*8 + 4];
      float a[8] = {a0.x,a0.y,a0.z,a0.w,a1.x,a1.y,a1.z,a1.w};
      float b0 = Bs[k][tc*2], b1 = Bs[k][tc*2 + 1];
      #pragma unroll
      for (int i = 0; i < 8; i++) { acc[i][0] += a[i]*b0; acc[i][1] += a[i]*b1; }
    }
    __syncthreads();
  }
  float bb0 = lb[tc*2], bb1 = lb[tc*2 + 1];
  #pragma unroll
  for (int i = 0; i < 8; i++) {
    int m = bm + tr*8 + i;
    if (m >= NN) continue;
    float v0 = acc[i][0] + bb0, v1 = acc[i][1] + bb1;
    if (do_pool) {
      int pb = g_batch[m]*DD;
      atomicMaxF(&g_pool[pb + tc*2],     v0);
      atomicMaxF(&g_pool[pb + tc*2 + 1], v1);
    } else {
      Cout[(size_t)m*DD + tc*2]     = v0;
      Cout[(size_t)m*DD + tc*2 + 1] = v1;
    }
  }
}

// ---------------- head MLP ----------------
__global__ void k_final(const float* __restrict__ fc1W, const float* __restrict__ fc1b,
                        const float* __restrict__ fc2W, const float* __restrict__ fc2b,
                        float* __restrict__ out) {
  int g = threadIdx.x;
  if (g >= GG) return;
  float y[DD];
  #pragma unroll
  for (int j = 0; j < DD; j++) {
    float acc = fc1b[j];
    #pragma unroll
    for (int k = 0; k < DD; k++) acc += g_pool[g*DD + k] * fc1W[j*DD + k];
    y[j] = fmaxf(acc, 0.f);
  }
  #pragma unroll
  for (int i = 0; i < TT; i++) {
    float acc = fc2b[i];
    #pragma unroll
    for (int j = 0; j < DD; j++) acc += y[j] * fc2W[i*DD + j];
    out[g*TT + i] = acc;
  }
}

// ---------------- driver ----------------
extern "C" void kernel_launch(void* const* d_in, const int* in_sizes, int n_in,
                              void* d_out, int out_size) {
  const float* x   = (const float*)d_in[0];
  const void*  ei  = d_in[1];
  const void*  bt  = d_in[2];
  const float* Wl0 = (const float*)d_in[3];  const float* bl0 = (const float*)d_in[4];
  const float* Wr0 = (const float*)d_in[5];  const float* br0 = (const float*)d_in[6];
  const float* at0 = (const float*)d_in[7];  const float* cb0 = (const float*)d_in[8];
  const float* lw0 = (const float*)d_in[9];  const float* lb0 = (const float*)d_in[10];
  const float* Wl1 = (const float*)d_in[11]; const float* bl1 = (const float*)d_in[12];
  const float* Wr1 = (const float*)d_in[13]; const float* br1 = (const float*)d_in[14];
  const float* at1 = (const float*)d_in[15]; const float* cb1 = (const float*)d_in[16];
  const float* lw1 = (const float*)d_in[17]; const float* lb1 = (const float*)d_in[18];
  const float* f1W = (const float*)d_in[19]; const float* f1b = (const float*)d_in[20];
  const float* f2W = (const float*)d_in[21]; const float* f2b = (const float*)d_in[22];
  float* out = (float*)d_out;

  float* hf;
  cudaGetSymbolAddress((void**)&hf, g_hfeat);

  const int prep_blocks = (EE + 255)/256;           // 1875
  const int lin_blocks  = (NN + 127)/128;           // 235

  k_gemm_prep<<<NGB + prep_blocks, 256>>>(x, Wl0, bl0, Wr0, br0, NN, FIN, ei, bt); // idx 0
  k_scan<<<1, 1024>>>();                            // idx 1
  k_fill<<<prep_blocks, 256>>>();                   // idx 2
  k_conv<<<NN/16, 256>>>(at0, cb0);                 // idx 3 -> profiled
  k_lin<<<lin_blocks, 256>>>(lw0, lb0, hf, 0);      // idx 4
  k_gemm_prep<<<NGB, 256>>>(hf, Wl1, bl1, Wr1, br1, NN, DD, ei, bt);  // idx 5
  k_conv<<<NN/16, 256>>>(at1, cb1);                 // idx 6
  k_lin<<<lin_blocks, 256>>>(lw1, lb1, nullptr, 1); // idx 7
  k_final<<<1, 128>>>(f1W, f1b, f2W, f2b, out);     // idx 8
}

// round 12
// speedup vs baseline: 1.9128x; 1.1102x over previous
#include <cuda_runtime.h>
#include <cuda_fp16.h>
#include <math.h>

#define NN 30000
#define EE 480000
#define CSRN (EE + NN)      // csr with self loops appended per row
#define FIN 128
#define DD 32
#define HH 4
#define HD 128
#define GG 128
#define TT 10
#define NGB 470             // gemm blocks: 2 * ceil(NN/128)

// ---------------- scratch (device globals; no allocation allowed) ----------------
__device__ __half g_xlh[NN*HD];    // xl in fp16 (conv gather operand)
__device__ float  g_xr[NN*HD];     // xr in fp32
__device__ float  g_tmp[NN*HD];    // conv output before the HD->DD linear
__device__ float  g_hfeat[NN*DD];
__device__ int2   g_sd[EE];        // packed (src,dst)
__device__ int    g_csr_src[CSRN];
__device__ int    g_deg[NN];       // zero at load; re-zeroed by k_scan each run
__device__ int    g_fill[NN];
__device__ int    g_rowptr[NN+1];  // self-loop-inclusive (shifted by +idx)
__device__ int    g_batch[NN];
__device__ float  g_pool[GG*DD];

// float atomic max via sign-split (correct incl. -0.0; init = -inf)
__device__ __forceinline__ void atomicMaxF(float* addr, float v) {
  unsigned u = __float_as_uint(v);
  if (u >> 31) atomicMin((unsigned*)addr, u);
  else         atomicMax((int*)addr, (int)u);
}

__device__ __forceinline__ float to_tf32(float x) {
  float y;
  asm("cvt.rna.tf32.f32 %0, %1;" : "=f"(y) : "f"(x));
  return y;
}

__device__ __forceinline__ void mma_tf32(float c[4],
    unsigned a0, unsigned a1, unsigned a2, unsigned a3,
    unsigned b0, unsigned b1) {
  asm volatile(
    "mma.sync.aligned.m16n8k8.row.col.f32.tf32.tf32.f32 "
    "{%0,%1,%2,%3}, {%4,%5,%6,%7}, {%8,%9}, {%0,%1,%2,%3};"
    : "+f"(c[0]), "+f"(c[1]), "+f"(c[2]), "+f"(c[3])
    : "r"(a0), "r"(a1), "r"(a2), "r"(a3), "r"(b0), "r"(b1));
}

// ---------------- fused: dual tf32-MMA GEMM (blocks < NGB) + edge prep (blocks >= NGB) ----------------
// GEMM: xl[m] = A@Wl^T+bl (fp16 out), xr[m] = A@Wr^T+br (fp32 out).
// BM=128, BN=128 (blockIdx&1: 0->xl, 1->xr), BK=16. 8 warps (4 Mx2 N), warp tile 32x64.
__global__ __launch_bounds__(256) void k_gemm_prep(
    const float* __restrict__ A,
    const float* __restrict__ Wl, const float* __restrict__ bl,
    const float* __restrict__ Wr, const float* __restrict__ br,
    int M, int K,
    const void* __restrict__ ei, const void* __restrict__ bt) {
  if (blockIdx.x >= NGB) {                 // ---- prep branch ----
    __shared__ int s64;
    if (threadIdx.x == 0) {
      const long long* p = (const long long*)ei;
      int ok = 1;
      #pragma unroll
      for (int q = 0; q < 16; q++) { long long v = p[q]; if (v < 0 || v >= NN) ok = 0; }
      s64 = ok;
    }
    __syncthreads();
    int is64 = s64;
    int i = (blockIdx.x - NGB)*256 + threadIdx.x;
    if (i < EE) {
      int s, d;
      if (is64) {
        const long long* p = (const long long*)ei;
        s = (int)p[i]; d = (int)p[EE + i];
      } else {
        const int* p = (const int*)ei;
        s = p[i]; d = p[EE + i];
      }
      g_sd[i] = make_int2(s, d);
      atomicAdd(&g_deg[d], 1);
    }
    if (i < NN)
      g_batch[i] = is64 ? (int)((const long long*)bt)[i] : ((const int*)bt)[i];
    if (i < GG*DD) g_pool[i] = -INFINITY;
    return;
  }
  // ---- GEMM branch (tf32 mma) ----
  __shared__ float As[16][132];   // [k][m], tf32-rounded
  __shared__ float Bs[16][132];   // [k][n], tf32-rounded (Bs[k][n] = W[n][k])
  const int bm = (blockIdx.x >> 1) * 128;
  const int half_out = (blockIdx.x & 1) == 0;   // 0 -> xl(half), 1 -> xr(float)
  const int tid = threadIdx.x;
  const int lane = tid & 31;
  const int wid = tid >> 5;
  const int warp_m = wid & 3;     // 32 rows each
  const int warp_n = wid >> 2;    // 64 cols each
  const float* W = half_out ? Wl : Wr;
  const float* bias = half_out ? bl : br;

  float c[2][8][4];
  #pragma unroll
  for (int mt = 0; mt < 2; mt++)
    #pragma unroll
    for (int nt = 0; nt < 8; nt++)
      #pragma unroll
      for (int q = 0; q < 4; q++) c[mt][nt][q] = 0.f;

  const int ar = lane >> 2;       // 0..7
  const int ac = lane & 3;        // 0..3

  for (int k0 = 0; k0 < K; k0 += 16) {
    #pragma unroll
    for (int i = 0; i < 2; i++) {
      int li = tid + i*256;
      int r = li >> 2;
      int kk = (li & 3) * 4;
      int m = bm + r;
      float4 v = make_float4(0.f,0.f,0.f,0.f);
      if (m < M) v = *(const float4*)&A[(size_t)m*K + k0 + kk];
      As[kk+0][r] = to_tf32(v.x); As[kk+1][r] = to_tf32(v.y);
      As[kk+2][r] = to_tf32(v.z); As[kk+3][r] = to_tf32(v.w);
    }
    #pragma unroll
    for (int i = 0; i < 2; i++) {
      int li = tid + i*256;
      int r = li >> 2;
      int kk = (li & 3) * 4;
      float4 v = *(const float4*)&W[(size_t)r*K + k0 + kk];
      Bs[kk+0][r] = to_tf32(v.x); Bs[kk+1][r] = to_tf32(v.y);
      Bs[kk+2][r] = to_tf32(v.z); Bs[kk+3][r] = to_tf32(v.w);
    }
    __syncthreads();
    #pragma unroll
    for (int ks = 0; ks < 16; ks += 8) {
      unsigned a[2][4];
      #pragma unroll
      for (int mt = 0; mt < 2; mt++) {
        int mb = warp_m*32 + mt*16;
        a[mt][0] = __float_as_uint(As[ks+ac  ][mb+ar  ]);
        a[mt][1] = __float_as_uint(As[ks+ac  ][mb+ar+8]);
        a[mt][2] = __float_as_uint(As[ks+ac+4][mb+ar  ]);
        a[mt][3] = __float_as_uint(As[ks+ac+4][mb+ar+8]);
      }
      #pragma unroll
      for (int nt = 0; nt < 8; nt++) {
        int nb = warp_n*64 + nt*8;
        unsigned b0 = __float_as_uint(Bs[ks+ac  ][nb+ar]);
        unsigned b1 = __float_as_uint(Bs[ks+ac+4][nb+ar]);
        mma_tf32(c[0][nt], a[0][0], a[0][1], a[0][2], a[0][3], b0, b1);
        mma_tf32(c[1][nt], a[1][0], a[1][1], a[1][2], a[1][3], b0, b1);
      }
    }
    __syncthreads();
  }

  // epilogue: c[mt][nt] rows (lane>>2, +8), cols 2*(lane&3), +1
  #pragma unroll
  for (int mt = 0; mt < 2; mt++) {
    #pragma unroll
    for (int nt = 0; nt < 8; nt++) {
      int n0 = warp_n*64 + nt*8 + 2*ac;
      float bb0 = bias[n0], bb1 = bias[n0+1];
      #pragma unroll
      for (int half2row = 0; half2row < 2; half2row++) {
        int m = bm + warp_m*32 + mt*16 + ar + half2row*8;
        if (m >= M) continue;
        float v0 = c[mt][nt][half2row*2+0] + bb0;
        float v1 = c[mt][nt][half2row*2+1] + bb1;
        if (half_out)
          *(__half2*)&g_xlh[(size_t)m*HD + n0] = __floats2half2_rn(v0, v1);
        else
          *(float2*)&g_xr[(size_t)m*HD + n0] = make_float2(v0, v1);
      }
    }
  }
}

// single-block scan (spill-free, two passes over g_deg) -> self-loop-inclusive rowptr
__global__ __launch_bounds__(1024) void k_scan() {
  __shared__ int ssum[1024];
  const int per = (NN + 1023)/1024;  // 30
  int t = threadIdx.x;
  int base = t*per;
  int local = 0;
  for (int i = 0; i < per; i++) {
    int idx = base + i;
    if (idx < NN) local += g_deg[idx];
  }
  ssum[t] = local;
  __syncthreads();
  for (int off = 1; off < 1024; off <<= 1) {
    int v = (t >= off) ? ssum[t-off] : 0;
    __syncthreads();
    ssum[t] += v;
    __syncthreads();
  }
  int run = (t == 0) ? 0 : ssum[t-1];
  for (int i = 0; i < per; i++) {
    int idx = base + i;
    if (idx < NN) {
      int v = g_deg[idx];
      g_deg[idx] = 0;                    // zero for next replay
      int rp = run + idx;                // +idx: one self-loop slot per preceding row
      g_rowptr[idx] = rp;
      g_fill[idx]   = rp;
      run += v;
    }
  }
  if (t == 1023) g_rowptr[NN] = ssum[1023] + NN;
}

// fill CSR edges (atomic position) + write self-loop at end of each row
__global__ void k_fill() {
  int i = blockIdx.x*blockDim.x + threadIdx.x;
  if (i < EE) {
    int2 sd = g_sd[i];
    int pos = atomicAdd(&g_fill[sd.y], 1);
    g_csr_src[pos] = sd.x;
  }
  if (i < NN)
    g_csr_src[g_rowptr[i+1] - 1] = i;    // self loop (slot rowptr[i]+deg, no conflict)
}

// ---------------- lean GATv2 conv: 2 nodes/warp, 16 lanes/node ----------------
__global__ __launch_bounds__(256) void k_conv(
    const float* __restrict__ att, const float* __restrict__ cb) {
  int t = threadIdx.x;
  int w = t >> 5, lane = t & 31;
  int half = lane >> 4, sl = lane & 15;
  int node = w*2 + half;
  int d = blockIdx.x*16 + node;           // grid = NN/16 = 1875 exactly

  float xr[8], at[8];
  {
    float4 a0 = *(const float4*)&g_xr[(size_t)d*HD + sl*8];
    float4 a1 = *(const float4*)&g_xr[(size_t)d*HD + sl*8 + 4];
    xr[0]=a0.x; xr[1]=a0.y; xr[2]=a0.z; xr[3]=a0.w;
    xr[4]=a1.x; xr[5]=a1.y; xr[6]=a1.z; xr[7]=a1.w;
    float4 b0 = *(const float4*)&att[sl*8];
    float4 b1 = *(const float4*)&att[sl*8 + 4];
    at[0]=b0.x; at[1]=b0.y; at[2]=b0.z; at[3]=b0.w;
    at[4]=b1.x; at[5]=b1.y; at[6]=b1.z; at[7]=b1.w;
  }
  float acc[8] = {0.f,0.f,0.f,0.f,0.f,0.f,0.f,0.f};
  float den = 0.f;
  int rs = __ldg(&g_rowptr[d]), re = __ldg(&g_rowptr[d+1]);
  int iters = re - rs;                    // >= 1 (self loop)
  int maxit = max(iters, __shfl_xor_sync(0xffffffffu, iters, 16));

  int s0 = __ldg(&g_csr_src[rs]);
  uint4 hc = *(const uint4*)&g_xlh[(size_t)s0*HD + sl*8];
  for (int i = 0; i < maxit; i++) {
    int nxt = (i + 1 < iters) ? rs + i + 1 : re - 1;
    int sn = __ldg(&g_csr_src[nxt]);
    uint4 hn = *(const uint4*)&g_xlh[(size_t)sn*HD + sl*8];   // prefetch next

    float f[8];
    float2 c0 = __half22float2(*(const __half2*)&hc.x);
    float2 c1 = __half22float2(*(const __half2*)&hc.y);
    float2 c2 = __half22float2(*(const __half2*)&hc.z);
    float2 c3 = __half22float2(*(const __half2*)&hc.w);
    f[0]=c0.x; f[1]=c0.y; f[2]=c1.x; f[3]=c1.y;
    f[4]=c2.x; f[5]=c2.y; f[6]=c3.x; f[7]=c3.y;

    float sum = 0.f;
    #pragma unroll
    for (int k = 0; k < 8; k++) {
      float v = f[k] + xr[k];
      v = fmaxf(v, 0.2f*v);               // leaky_relu(0.2)
      sum += v * at[k];
    }
    sum += __shfl_xor_sync(0xffffffffu, sum, 1);
    sum += __shfl_xor_sync(0xffffffffu, sum, 2);  // head alpha in each 4-lane group
    float ex = (i < iters) ? __expf(sum) : 0.f;
    den += ex;
    #pragma unroll
    for (int k = 0; k < 8; k++) acc[k] += ex * f[k];
    hc = hn;
  }

  float inv = 1.0f / (den * (float)iters);        // mean over deg+1 (self incl.)
  float4 cb0 = *(const float4*)&cb[sl*8];
  float4 cb1 = *(const float4*)&cb[sl*8 + 4];
  float4 o0 = make_float4(acc[0]*inv + cb0.x, acc[1]*inv + cb0.y,
                          acc[2]*inv + cb0.z, acc[3]*inv + cb0.w);
  float4 o1 = make_float4(acc[4]*inv + cb1.x, acc[5]*inv + cb1.y,
                          acc[6]*inv + cb1.z, acc[7]*inv + cb1.w);
  *(float4*)&g_tmp[(size_t)d*HD + sl*8]     = o0;
  *(float4*)&g_tmp[(size_t)d*HD + sl*8 + 4] = o1;
}

// ---------------- HD->DD linear as tiled GEMM: C = tmp @ lw^T + lb ----------------
__global__ __launch_bounds__(256) void k_lin(
    const float* __restrict__ lw, const float* __restrict__ lb,
    float* __restrict__ Cout, int do_pool) {
  __shared__ float As[16][132];
  __shared__ float Bs[16][36];
  const int bm = blockIdx.x * 128;
  const int tid = threadIdx.x;
  const int tr = tid >> 4;      // 0..15 -> 8 rows each
  const int tc = tid & 15;      // 0..15 -> 2 cols each
  float acc[8][2] = {};
  for (int k0 = 0; k0 < HD; k0 += 16) {
    #pragma unroll
    for (int i = 0; i < 2; i++) {
      int li = tid + i*256;
      int r = li >> 2;
      int kk = (li & 3) * 4;
      int m = bm + r;
      float4 v = make_float4(0.f,0.f,0.f,0.f);
      if (m < NN) v = *(const float4*)&g_tmp[(size_t)m*HD + k0 + kk];
      As[kk+0][r] = v.x; As[kk+1][r] = v.y; As[kk+2][r] = v.z; As[kk+3][r] = v.w;
    }
    if (tid < 128) {
      int r = tid >> 2;         // 0..31
      int kk = (tid & 3) * 4;
      float4 v = *(const float4*)&lw[(size_t)r*HD + k0 + kk];
      Bs[kk+0][r] = v.x; Bs[kk+1][r] = v.y; Bs[kk+2][r] = v.z; Bs[kk+3][r] = v.w;
    }
    __syncthreads();
    #pragma unroll
    for (int k = 0; k < 16; k++) {
      float4 a0 = *(const float4*)&As[k][tr*8];
      float4 a1 = *(const float4*)&As[k][tr*8 + 4];
      float a[8] = {a0.x,a0.y,a0.z,a0.w,a1.x,a1.y,a1.z,a1.w};
      float b0 = Bs[k][tc*2], b1 = Bs[k][tc*2 + 1];
      #pragma unroll
      for (int i = 0; i < 8; i++) { acc[i][0] += a[i]*b0; acc[i][1] += a[i]*b1; }
    }
    __syncthreads();
  }
  float bb0 = lb[tc*2], bb1 = lb[tc*2 + 1];
  #pragma unroll
  for (int i = 0; i < 8; i++) {
    int m = bm + tr*8 + i;
    if (m >= NN) continue;
    float v0 = acc[i][0] + bb0, v1 = acc[i][1] + bb1;
    if (do_pool) {
      int pb = g_batch[m]*DD;
      atomicMaxF(&g_pool[pb + tc*2],     v0);
      atomicMaxF(&g_pool[pb + tc*2 + 1], v1);
    } else {
      Cout[(size_t)m*DD + tc*2]     = v0;
      Cout[(size_t)m*DD + tc*2 + 1] = v1;
    }
  }
}

// ---------------- head MLP ----------------
__global__ void k_final(const float* __restrict__ fc1W, const float* __restrict__ fc1b,
                        const float* __restrict__ fc2W, const float* __restrict__ fc2b,
                        float* __restrict__ out) {
  int g = threadIdx.x;
  if (g >= GG) return;
  float y[DD];
  #pragma unroll
  for (int j = 0; j < DD; j++) {
    float acc = fc1b[j];
    #pragma unroll
    for (int k = 0; k < DD; k++) acc += g_pool[g*DD + k] * fc1W[j*DD + k];
    y[j] = fmaxf(acc, 0.f);
  }
  #pragma unroll
  for (int i = 0; i < TT; i++) {
    float acc = fc2b[i];
    #pragma unroll
    for (int j = 0; j < DD; j++) acc += y[j] * fc2W[i*DD + j];
    out[g*TT + i] = acc;
  }
}

// ---------------- driver ----------------
extern "C" void kernel_launch(void* const* d_in, const int* in_sizes, int n_in,
                              void* d_out, int out_size) {
  const float* x   = (const float*)d_in[0];
  const void*  ei  = d_in[1];
  const void*  bt  = d_in[2];
  const float* Wl0 = (const float*)d_in[3];  const float* bl0 = (const float*)d_in[4];
  const float* Wr0 = (const float*)d_in[5];  const float* br0 = (const float*)d_in[6];
  const float* at0 = (const float*)d_in[7];  const float* cb0 = (const float*)d_in[8];
  const float* lw0 = (const float*)d_in[9];  const float* lb0 = (const float*)d_in[10];
  const float* Wl1 = (const float*)d_in[11]; const float* bl1 = (const float*)d_in[12];
  const float* Wr1 = (const float*)d_in[13]; const float* br1 = (const float*)d_in[14];
  const float* at1 = (const float*)d_in[15]; const float* cb1 = (const float*)d_in[16];
  const float* lw1 = (const float*)d_in[17]; const float* lb1 = (const float*)d_in[18];
  const float* f1W = (const float*)d_in[19]; const float* f1b = (const float*)d_in[20];
  const float* f2W = (const float*)d_in[21]; const float* f2b = (const float*)d_in[22];
  float* out = (float*)d_out;

  float* hf;
  cudaGetSymbolAddress((void**)&hf, g_hfeat);

  const int prep_blocks = (EE + 255)/256;           // 1875
  const int lin_blocks  = (NN + 127)/128;           // 235

  k_gemm_prep<<<NGB + prep_blocks, 256>>>(x, Wl0, bl0, Wr0, br0, NN, FIN, ei, bt); // idx 0
  k_scan<<<1, 1024>>>();                            // idx 1
  k_fill<<<prep_blocks, 256>>>();                   // idx 2
  k_conv<<<NN/16, 256>>>(at0, cb0);                 // idx 3 -> profiled
  k_lin<<<lin_blocks, 256>>>(lw0, lb0, hf, 0);      // idx 4
  k_gemm_prep<<<NGB, 256>>>(hf, Wl1, bl1, Wr1, br1, NN, DD, ei, bt);  // idx 5
  k_conv<<<NN/16, 256>>>(at1, cb1);                 // idx 6
  k_lin<<<lin_blocks, 256>>>(lw1, lb1, nullptr, 1); // idx 7
  k_final<<<1, 128>>>(f1W, f1b, f2W, f2b, out);     // idx 8
}

// round 14
// speedup vs baseline: 2.0201x; 1.0561x over previous
#include <cuda_runtime.h>
#include <cuda_fp16.h>
#include <math.h>

#define NN 30000
#define EE 480000
#define CSRN (EE + NN)
#define FIN 128
#define DD 32
#define HH 4
#define HD 128
#define GG 128
#define TT 10
#define NGB 235             // gemm blocks: ceil(NN/128)

// ---------------- scratch (device globals; no allocation allowed) ----------------
__device__ __half g_xlh[NN*HD];    // xl in fp16 (conv gather operand)
__device__ float  g_xr[NN*HD];     // xr in fp32
__device__ float  g_tmp[NN*HD];    // conv output before the HD->DD linear
__device__ float  g_hfeat[NN*DD];
__device__ int2   g_sd[EE];
__device__ int    g_csr_src[CSRN];
__device__ int    g_deg[NN];       // zero at load; re-zeroed by k_scan each run
__device__ int    g_fill[NN];
__device__ int    g_rowptr[NN+1];
__device__ int    g_batch[NN];
__device__ float  g_pool[GG*DD];

__device__ __forceinline__ void atomicMaxF(float* addr, float v) {
  unsigned u = __float_as_uint(v);
  if (u >> 31) atomicMin((unsigned*)addr, u);
  else         atomicMax((int*)addr, (int)u);
}

__device__ __forceinline__ void mma_f16(float c[4],
    unsigned a0, unsigned a1, unsigned a2, unsigned a3,
    unsigned b0, unsigned b1) {
  asm volatile(
    "mma.sync.aligned.m16n8k16.row.col.f32.f16.f16.f32 "
    "{%0,%1,%2,%3}, {%4,%5,%6,%7}, {%8,%9}, {%0,%1,%2,%3};"
    : "+f"(c[0]), "+f"(c[1]), "+f"(c[2]), "+f"(c[3])
    : "r"(a0), "r"(a1), "r"(a2), "r"(a3), "r"(b0), "r"(b1));
}

// ---------------- fused: fp16-HMMA dual GEMM (blocks < NGB) + edge prep ----------------
// GEMM: out[m][0:128)=A@Wl^T+bl -> g_xlh (fp16), out[m][128:256)=A@Wr^T+br -> g_xr (fp32).
// 512 threads = 16 warps. Block tile 128x256, BK=16. Warp tile 32x64 (wm=wid&3, wn=wid>>2).
__global__ __launch_bounds__(512) void k_gemm_prep(
    const float* __restrict__ A,
    const float* __restrict__ Wl, const float* __restrict__ bl,
    const float* __restrict__ Wr, const float* __restrict__ br,
    int K,
    const void* __restrict__ ei, const void* __restrict__ bt) {
  __shared__ __half As[128][24];     // [m][k], pad to 24 halves (48B rows)
  __shared__ __half Bs[256][24];     // [n][k]
  __shared__ float  sbias[256];
  if (blockIdx.x >= NGB) {           // ---- prep branch ----
    __shared__ int s64;
    if (threadIdx.x == 0) {
      const long long* p = (const long long*)ei;
      int ok = 1;
      #pragma unroll
      for (int q = 0; q < 16; q++) { long long v = p[q]; if (v < 0 || v >= NN) ok = 0; }
      s64 = ok;
    }
    __syncthreads();
    int is64 = s64;
    int i = (blockIdx.x - NGB)*512 + threadIdx.x;
    if (i < EE) {
      int s, d;
      if (is64) {
        const long long* p = (const long long*)ei;
        s = (int)p[i]; d = (int)p[EE + i];
      } else {
        const int* p = (const int*)ei;
        s = p[i]; d = p[EE + i];
      }
      g_sd[i] = make_int2(s, d);
      atomicAdd(&g_deg[d], 1);
    }
    if (i < NN)
      g_batch[i] = is64 ? (int)((const long long*)bt)[i] : ((const int*)bt)[i];
    if (i < GG*DD) g_pool[i] = -INFINITY;
    return;
  }
  // ---- GEMM branch ----
  const int tid = threadIdx.x;
  const int lane = tid & 31;
  const int wid = tid >> 5;
  const int warp_m = wid & 3;        // 4 x 32 rows
  const int warp_n = wid >> 2;       // 4 x 64 cols
  const int bm = blockIdx.x * 128;
  const int g8 = lane >> 2;          // groupID 0..7
  const int t4 = lane & 3;           // threadID in group 0..3

  if (tid < 256) sbias[tid] = (tid < 128) ? bl[tid] : br[tid - 128];

  float c[2][8][4];
  #pragma unroll
  for (int mt = 0; mt < 2; mt++)
    #pragma unroll
    for (int nt = 0; nt < 8; nt++)
      #pragma unroll
      for (int q = 0; q < 4; q++) c[mt][nt][q] = 0.f;

  for (int k0 = 0; k0 < K; k0 += 16) {
    {  // A tile: 128 x 16 fp32 -> fp16
      int r = tid >> 2;
      int kk = (tid & 3) * 4;
      int m = bm + r;
      float4 v = make_float4(0.f,0.f,0.f,0.f);
      if (m < NN) v = *(const float4*)&A[(size_t)m*K + k0 + kk];
      __half2 h01 = __floats2half2_rn(v.x, v.y);
      __half2 h23 = __floats2half2_rn(v.z, v.w);
      *(__half2*)&As[r][kk]     = h01;
      *(__half2*)&As[r][kk + 2] = h23;
    }
    #pragma unroll
    for (int i = 0; i < 2; i++) {    // B tile: 256 x 16
      int li = tid + i*512;
      int r = li >> 2;
      int kk = (li & 3) * 4;
      const float* Wrow = (r < 128) ? &Wl[(size_t)r*K] : &Wr[(size_t)(r-128)*K];
      float4 v = *(const float4*)&Wrow[k0 + kk];
      __half2 h01 = __floats2half2_rn(v.x, v.y);
      __half2 h23 = __floats2half2_rn(v.z, v.w);
      *(__half2*)&Bs[r][kk]     = h01;
      *(__half2*)&Bs[r][kk + 2] = h23;
    }
    __syncthreads();

    unsigned a[2][4];
    #pragma unroll
    for (int mt = 0; mt < 2; mt++) {
      int mb = warp_m*32 + mt*16;
      a[mt][0] = *(const unsigned*)&As[mb + g8    ][2*t4    ];
      a[mt][1] = *(const unsigned*)&As[mb + g8 + 8][2*t4    ];
      a[mt][2] = *(const unsigned*)&As[mb + g8    ][2*t4 + 8];
      a[mt][3] = *(const unsigned*)&As[mb + g8 + 8][2*t4 + 8];
    }
    #pragma unroll
    for (int nt = 0; nt < 8; nt++) {
      int nb = warp_n*64 + nt*8;
      unsigned b0 = *(const unsigned*)&Bs[nb + g8][2*t4    ];
      unsigned b1 = *(const unsigned*)&Bs[nb + g8][2*t4 + 8];
      mma_f16(c[0][nt], a[0][0], a[0][1], a[0][2], a[0][3], b0, b1);
      mma_f16(c[1][nt], a[1][0], a[1][1], a[1][2], a[1][3], b0, b1);
    }
    __syncthreads();
  }

  // epilogue: c[mt][nt]: rows g8 (+8), cols 2*t4 (+1)
  #pragma unroll
  for (int mt = 0; mt < 2; mt++) {
    #pragma unroll
    for (int nt = 0; nt < 8; nt++) {
      int n0 = warp_n*64 + nt*8 + 2*t4;
      float bb0 = sbias[n0], bb1 = sbias[n0+1];
      #pragma unroll
      for (int rr = 0; rr < 2; rr++) {
        int m = bm + warp_m*32 + mt*16 + g8 + rr*8;
        if (m >= NN) continue;
        float v0 = c[mt][nt][rr*2+0] + bb0;
        float v1 = c[mt][nt][rr*2+1] + bb1;
        if (n0 < 128)
          *(__half2*)&g_xlh[(size_t)m*HD + n0] = __floats2half2_rn(v0, v1);
        else
          *(float2*)&g_xr[(size_t)m*HD + (n0 - 128)] = make_float2(v0, v1);
      }
    }
  }
}

// single-block spill-free scan -> self-loop-inclusive rowptr; seeds g_fill; re-zeroes g_deg
__global__ __launch_bounds__(1024) void k_scan() {
  __shared__ int ssum[1024];
  const int per = (NN + 1023)/1024;
  int t = threadIdx.x;
  int base = t*per;
  int local = 0;
  for (int i = 0; i < per; i++) {
    int idx = base + i;
    if (idx < NN) local += g_deg[idx];
  }
  ssum[t] = local;
  __syncthreads();
  for (int off = 1; off < 1024; off <<= 1) {
    int v = (t >= off) ? ssum[t-off] : 0;
    __syncthreads();
    ssum[t] += v;
    __syncthreads();
  }
  int run = (t == 0) ? 0 : ssum[t-1];
  for (int i = 0; i < per; i++) {
    int idx = base + i;
    if (idx < NN) {
      int v = g_deg[idx];
      g_deg[idx] = 0;
      int rp = run + idx;
      g_rowptr[idx] = rp;
      g_fill[idx]   = rp;
      run += v;
    }
  }
  if (t == 1023) g_rowptr[NN] = ssum[1023] + NN;
}

__global__ void k_fill() {
  int i = blockIdx.x*blockDim.x + threadIdx.x;
  if (i < EE) {
    int2 sd = g_sd[i];
    int pos = atomicAdd(&g_fill[sd.y], 1);
    g_csr_src[pos] = sd.x;
  }
  if (i < NN)
    g_csr_src[g_rowptr[i+1] - 1] = i;    // self loop at end of row
}

// ---------------- lean GATv2 conv: 2 nodes/warp, 16 lanes/node ----------------
__global__ __launch_bounds__(256) void k_conv(
    const float* __restrict__ att, const float* __restrict__ cb) {
  int t = threadIdx.x;
  int w = t >> 5, lane = t & 31;
  int half = lane >> 4, sl = lane & 15;
  int node = w*2 + half;
  int d = blockIdx.x*16 + node;

  float xr[8], at[8];
  {
    float4 a0 = *(const float4*)&g_xr[(size_t)d*HD + sl*8];
    float4 a1 = *(const float4*)&g_xr[(size_t)d*HD + sl*8 + 4];
    xr[0]=a0.x; xr[1]=a0.y; xr[2]=a0.z; xr[3]=a0.w;
    xr[4]=a1.x; xr[5]=a1.y; xr[6]=a1.z; xr[7]=a1.w;
    float4 b0 = *(const float4*)&att[sl*8];
    float4 b1 = *(const float4*)&att[sl*8 + 4];
    at[0]=b0.x; at[1]=b0.y; at[2]=b0.z; at[3]=b0.w;
    at[4]=b1.x; at[5]=b1.y; at[6]=b1.z; at[7]=b1.w;
  }
  float acc[8] = {0.f,0.f,0.f,0.f,0.f,0.f,0.f,0.f};
  float den = 0.f;
  int rs = __ldg(&g_rowptr[d]), re = __ldg(&g_rowptr[d+1]);
  int iters = re - rs;
  int maxit = max(iters, __shfl_xor_sync(0xffffffffu, iters, 16));

  int s0 = __ldg(&g_csr_src[rs]);
  uint4 hc = *(const uint4*)&g_xlh[(size_t)s0*HD + sl*8];
  for (int i = 0; i < maxit; i++) {
    int nxt = (i + 1 < iters) ? rs + i + 1 : re - 1;
    int sn = __ldg(&g_csr_src[nxt]);
    uint4 hn = *(const uint4*)&g_xlh[(size_t)sn*HD + sl*8];

    float f[8];
    float2 c0 = __half22float2(*(const __half2*)&hc.x);
    float2 c1 = __half22float2(*(const __half2*)&hc.y);
    float2 c2 = __half22float2(*(const __half2*)&hc.z);
    float2 c3 = __half22float2(*(const __half2*)&hc.w);
    f[0]=c0.x; f[1]=c0.y; f[2]=c1.x; f[3]=c1.y;
    f[4]=c2.x; f[5]=c2.y; f[6]=c3.x; f[7]=c3.y;

    float sum = 0.f;
    #pragma unroll
    for (int k = 0; k < 8; k++) {
      float v = f[k] + xr[k];
      v = fmaxf(v, 0.2f*v);
      sum += v * at[k];
    }
    sum += __shfl_xor_sync(0xffffffffu, sum, 1);
    sum += __shfl_xor_sync(0xffffffffu, sum, 2);
    float ex = (i < iters) ? __expf(sum) : 0.f;
    den += ex;
    #pragma unroll
    for (int k = 0; k < 8; k++) acc[k] += ex * f[k];
    hc = hn;
  }

  float inv = 1.0f / (den * (float)iters);
  float4 cb0 = *(const float4*)&cb[sl*8];
  float4 cb1 = *(const float4*)&cb[sl*8 + 4];
  float4 o0 = make_float4(acc[0]*inv + cb0.x, acc[1]*inv + cb0.y,
                          acc[2]*inv + cb0.z, acc[3]*inv + cb0.w);
  float4 o1 = make_float4(acc[4]*inv + cb1.x, acc[5]*inv + cb1.y,
                          acc[6]*inv + cb1.z, acc[7]*inv + cb1.w);
  *(float4*)&g_tmp[(size_t)d*HD + sl*8]     = o0;
  *(float4*)&g_tmp[(size_t)d*HD + sl*8 + 4] = o1;
}

// ---------------- HD->DD linear as tiled GEMM: C = tmp @ lw^T + lb ----------------
__global__ __launch_bounds__(256) void k_lin(
    const float* __restrict__ lw, const float* __restrict__ lb,
    float* __restrict__ Cout, int do_pool) {
  __shared__ float As[16][132];
  __shared__ float Bs[16][36];
  const int bm = blockIdx.x * 128;
  const int tid = threadIdx.x;
  const int tr = tid >> 4;
  const int tc = tid & 15;
  float acc[8][2] = {};
  for (int k0 = 0; k0 < HD; k0 += 16) {
    #pragma unroll
    for (int i = 0; i < 2; i++) {
      int li = tid + i*256;
      int r = li >> 2;
      int kk = (li & 3) * 4;
      int m = bm + r;
      float4 v = make_float4(0.f,0.f,0.f,0.f);
      if (m < NN) v = *(const float4*)&g_tmp[(size_t)m*HD + k0 + kk];
      As[kk+0][r] = v.x; As[kk+1][r] = v.y; As[kk+2][r] = v.z; As[kk+3][r] = v.w;
    }
    if (tid < 128) {
      int r = tid >> 2;
      int kk = (tid & 3) * 4;
      float4 v = *(const float4*)&lw[(size_t)r*HD + k0 + kk];
      Bs[kk+0][r] = v.x; Bs[kk+1][r] = v.y; Bs[kk+2][r] = v.z; Bs[kk+3][r] = v.w;
    }
    __syncthreads();
    #pragma unroll
    for (int k = 0; k < 16; k++) {
      float4 a0 = *(const float4*)&As[k][tr*8];
      float4 a1 = *(const float4*)&As[k][tr*8 + 4];
      float a[8] = {a0.x,a0.y,a0.z,a0.w,a1.x,a1.y,a1.z,a1.w};
      float b0 = Bs[k][tc*2], b1 = Bs[k][tc*2 + 1];
      #pragma unroll
      for (int i = 0; i < 8; i++) { acc[i][0] += a[i]*b0; acc[i][1] += a[i]*b1; }
    }
    __syncthreads();
  }
  float bb0 = lb[tc*2], bb1 = lb[tc*2 + 1];
  #pragma unroll
  for (int i = 0; i < 8; i++) {
    int m = bm + tr*8 + i;
    if (m >= NN) continue;
    float v0 = acc[i][0] + bb0, v1 = acc[i][1] + bb1;
    if (do_pool) {
      int pb = g_batch[m]*DD;
      atomicMaxF(&g_pool[pb + tc*2],     v0);
      atomicMaxF(&g_pool[pb + tc*2 + 1], v1);
    } else {
      Cout[(size_t)m*DD + tc*2]     = v0;
      Cout[(size_t)m*DD + tc*2 + 1] = v1;
    }
  }
}

// ---------------- head MLP ----------------
__global__ void k_final(const float* __restrict__ fc1W, const float* __restrict__ fc1b,
                        const float* __restrict__ fc2W, const float* __restrict__ fc2b,
                        float* __restrict__ out) {
  int g = threadIdx.x;
  if (g >= GG) return;
  float y[DD];
  #pragma unroll
  for (int j = 0; j < DD; j++) {
    float acc = fc1b[j];
    #pragma unroll
    for (int k = 0; k < DD; k++) acc += g_pool[g*DD + k] * fc1W[j*DD + k];
    y[j] = fmaxf(acc, 0.f);
  }
  #pragma unroll
  for (int i = 0; i < TT; i++) {
    float acc = fc2b[i];
    #pragma unroll
    for (int j = 0; j < DD; j++) acc += y[j] * fc2W[i*DD + j];
    out[g*TT + i] = acc;
  }
}

// ---------------- driver ----------------
extern "C" void kernel_launch(void* const* d_in, const int* in_sizes, int n_in,
                              void* d_out, int out_size) {
  const float* x   = (const float*)d_in[0];
  const void*  ei  = d_in[1];
  const void*  bt  = d_in[2];
  const float* Wl0 = (const float*)d_in[3];  const float* bl0 = (const float*)d_in[4];
  const float* Wr0 = (const float*)d_in[5];  const float* br0 = (const float*)d_in[6];
  const float* at0 = (const float*)d_in[7];  const float* cb0 = (const float*)d_in[8];
  const float* lw0 = (const float*)d_in[9];  const float* lb0 = (const float*)d_in[10];
  const float* Wl1 = (const float*)d_in[11]; const float* bl1 = (const float*)d_in[12];
  const float* Wr1 = (const float*)d_in[13]; const float* br1 = (const float*)d_in[14];
  const float* at1 = (const float*)d_in[15]; const float* cb1 = (const float*)d_in[16];
  const float* lw1 = (const float*)d_in[17]; const float* lb1 = (const float*)d_in[18];
  const float* f1W = (const float*)d_in[19]; const float* f1b = (const float*)d_in[20];
  const float* f2W = (const float*)d_in[21]; const float* f2b = (const float*)d_in[22];
  float* out = (float*)d_out;

  float* hf;
  cudaGetSymbolAddress((void**)&hf, g_hfeat);

  const int prep512 = (EE + 511)/512;               // 938
  const int fillb   = (EE + 255)/256;               // 1875
  const int lin_blocks = (NN + 127)/128;            // 235

  // idx 0: gemm0 (HMMA) + prep fused
  k_gemm_prep<<<NGB + prep512, 512>>>(x, Wl0, bl0, Wr0, br0, FIN, ei, bt);
  k_scan<<<1, 1024>>>();                            // idx 1
  k_fill<<<fillb, 256>>>();                         // idx 2
  k_conv<<<NN/16, 256>>>(at0, cb0);                 // idx 3 -> profiled
  k_lin<<<lin_blocks, 256>>>(lw0, lb0, hf, 0);      // idx 4
  k_gemm_prep<<<NGB, 512>>>(hf, Wl1, bl1, Wr1, br1, DD, ei, bt);  // idx 5
  k_conv<<<NN/16, 256>>>(at1, cb1);                 // idx 6
  k_lin<<<lin_blocks, 256>>>(lw1, lb1, nullptr, 1); // idx 7
  k_final<<<1, 128>>>(f1W, f1b, f2W, f2b, out);     // idx 8
}